// round 16
// baseline (speedup 1.0000x reference)
#include <cuda_runtime.h>
#include <mma.h>
#include <math.h>
#include <cstdint>

using namespace nvcuda;

#define Bb 16
#define Cc 64
#define Hh 256
#define Ww 256
#define MM 16
#define SS 32

// ---------------- scratch ----------------------------------------------------
__device__ float2 d_tw[256];
__device__ float  d_TB[256*36];          // fwd trig (W), [w][ky2] pad, tf32-RNA
__device__ float  d_TE[32*256];          // inv trig (W), [kk][w], tf32-RNA
__device__ float  d_T2[64*260];          // fwd trig (H), [kx2][h] pad, tf32-RNA
__device__ float  d_TEH[256*68];         // inv trig (H), [h][kx2] pad, tf32-RNA
__device__ float  d_cwT[64*64];          // tf32(conv_w^T + I), [i][o]
__device__ float2 d_Xw[Bb*Cc*Hh*MM];
__device__ float2 d_Xf[Bb*Cc*SS*MM];
__device__ float2 d_Y [Bb*Cc*SS*MM];
__device__ float2 d_Z [Bb*Hh*Cc*MM];
__device__ float2 d_wt[2*256*4096];
__device__ float  d_partS[Bb*32*512];
__device__ float  d_partQ[Bb*32*512];
__device__ float2 d_stat[Bb*32];

__device__ __forceinline__ uint32_t f2tf32(float f) {
    uint32_t r; asm("cvt.rna.tf32.f32 %0, %1;" : "=r"(r) : "f"(f)); return r;
}
__device__ __forceinline__ uint32_t smem_u32(const void* p) {
    uint32_t a;
    asm("{ .reg .u64 t; cvta.to.shared.u64 t, %1; cvt.u32.u64 %0, t; }" : "=r"(a) : "l"(p));
    return a;
}
__device__ __forceinline__ void cp16(uint32_t dst, const void* src) {
    asm volatile("cp.async.ca.shared.global [%0], [%1], 16;" :: "r"(dst), "l"(src));
}
#define CP_COMMIT()  asm volatile("cp.async.commit_group;" ::: "memory")
#define CP_WAIT(n)   asm volatile("cp.async.wait_group %0;" :: "n"(n) : "memory")

// ---------------- init: twiddles + tf32 trig tables ----------------------------
__global__ void k_init() {
    int t = threadIdx.x;
    float s, c;
    sincospif((float)t * (1.0f / 128.0f), &s, &c);
    d_tw[t] = make_float2(c, s);
#pragma unroll
    for (int kk = 0; kk < 32; kk++) {
        int ky = kk >> 1;
        float s2, c2;
        sincospif((float)((ky * t) & 255) * (1.0f / 128.0f), &s2, &c2);
        d_TB[t * 36 + kk] = __uint_as_float(f2tf32((kk & 1) ? -s2 : c2));
        d_TE[kk * 256 + t] = __uint_as_float(f2tf32((kk & 1) ?  s2 : c2));
    }
    d_TB[t * 36 + 32] = 0.f; d_TB[t * 36 + 33] = 0.f;
    d_TB[t * 36 + 34] = 0.f; d_TB[t * 36 + 35] = 0.f;
    // H-axis forward: rows 2*kxi = cos, 2*kxi+1 = sin
    for (int idx = t; idx < 64 * 260; idx += 256) {
        int m = idx / 260, h = idx % 260;
        int kxi = m >> 1;
        int kx = (kxi < 16) ? kxi : (224 + kxi);
        float v = 0.f;
        if (h < 256) {
            float s3, c3;
            sincospif((float)((kx * h) & 255) * (1.0f / 128.0f), &s3, &c3);
            v = (m & 1) ? s3 : c3;
        }
        d_T2[idx] = __uint_as_float(f2tf32(v));
    }
    // H-axis inverse: [h][col], col 2k = cos(kx h), 2k+1 = sin(kx h); pad cols 64..67
    for (int idx = t; idx < 256 * 68; idx += 256) {
        int h = idx / 68, col = idx % 68;
        float v = 0.f;
        if (col < 64) {
            int kxi = col >> 1;
            int kx = (kxi < 16) ? kxi : (224 + kxi);
            float s4, c4;
            sincospif((float)((kx * h) & 255) * (1.0f / 128.0f), &s4, &c4);
            v = (col & 1) ? s4 : c4;
        }
        d_TEH[idx] = __uint_as_float(f2tf32(v));
    }
}

// ---------------- weight transpose --------------------------------------------
__global__ void k_transpose_w(const float* __restrict__ w1r, const float* __restrict__ w1i,
                              const float* __restrict__ w2r, const float* __restrict__ w2i) {
    int n = blockIdx.x * 256 + threadIdx.x;
    int half = n >> 20;
    int rem  = n & ((1 << 20) - 1);
    int mode = rem >> 12;
    int io   = rem & 4095;
    int kx = mode >> 4, ky = mode & 15;
    int i = io >> 6, o = io & 63;
    int src = ((i * 64 + o) * 16 + kx) * 16 + ky;
    const float* wr = half ? w2r : w1r;
    const float* wi = half ? w2i : w1i;
    d_wt[n] = make_float2(wr[src], wi[src]);
}

// ---------------- prep conv B (also profiling spacer) ---------------------------
__global__ void k_prepB(const float* __restrict__ cw) {
    int idx = blockIdx.x * 256 + threadIdx.x;
    int i = idx >> 6, o = idx & 63;
    float wv = cw[o * 64 + i] + ((i == o) ? 1.0f : 0.0f);
    d_cwT[idx] = __uint_as_float(f2tf32(wv));
}

// ---------------- stage A v3: DFT over W (champion) -----------------------------
#define LDX 260
#define LDTB 36
#define DW3_SMEM (25856*4)
__global__ void __launch_bounds__(256, 2)
k_dftW3(const float* __restrict__ x) {
    extern __shared__ float sm[];
    uint32_t sb = smem_u32(sm);
    int bx = blockIdx.x;
    int bc = bx >> 2, slab = bx & 3;
    int t = threadIdx.x, wid = t >> 5;
    float* sB = sm + 16640;
    const float* xblk = x + (size_t)bc * 65536 + slab * 16384;

#pragma unroll
    for (int j = 0; j < 16; j++) {
        int u = j * 256 + t;
        int hl = u >> 6, wu = u & 63;
        cp16(sb + (hl * LDX + wu * 4) * 4, xblk + hl * 256 + wu * 4);
    }
#pragma unroll
    for (int j = 0; j < 9; j++) {
        int u = j * 256 + t;
        cp16(sb + (16640 + u * 4) * 4, d_TB + u * 4);
    }
    CP_COMMIT();
    CP_WAIT(0);
    __syncthreads();

    int m_t = wid >> 1;
    int n_t = wid & 1;
    wmma::fragment<wmma::accumulator, 16, 16, 8, float> acc;
    wmma::fill_fragment(acc, 0.0f);
#pragma unroll
    for (int k0 = 0; k0 < 32; k0++) {
        wmma::fragment<wmma::matrix_a, 16, 16, 8, wmma::precision::tf32, wmma::row_major> af;
        wmma::fragment<wmma::matrix_b, 16, 16, 8, wmma::precision::tf32, wmma::row_major> bf;
        wmma::load_matrix_sync(af, sm + (m_t * 16) * LDX + k0 * 8, LDX);
        wmma::load_matrix_sync(bf, sB + (k0 * 8) * LDTB + n_t * 16, LDTB);
        wmma::mma_sync(acc, af, bf, acc);
    }
    __syncthreads();
    float* sC = sm;
    wmma::store_matrix_sync(sC + (m_t * 16) * LDTB + n_t * 16, acc, LDTB,
                            wmma::mem_row_major);
    __syncthreads();

    float4* dst = (float4*)(d_Xw + ((size_t)(bc << 8) + slab * 64) * 16);
#pragma unroll
    for (int r = 0; r < 2; r++) {
        int u = r * 256 + t;
        int row = u >> 3, c4 = u & 7;
        dst[row * 8 + c4] = *(float4*)&sC[row * LDTB + c4 * 4];
    }
}

// ---------------- stage B v2: DFT over H (champion) ------------------------------
#define DH_SMEM (25856*4)
__global__ void __launch_bounds__(256, 2)
k_dftH2() {
    extern __shared__ float sm[];
    uint32_t sb = smem_u32(sm);
    int bc = blockIdx.x;
    int t = threadIdx.x, wid = t >> 5;
    float* sX = sm + 16640;

#pragma unroll
    for (int j = 0; j < 17; j++) {
        int u = j * 256 + t;
        if (u < 4160) cp16(sb + u * 16, d_T2 + u * 4);
    }
    const float* xw = (const float*)(d_Xw + (size_t)bc * 4096);
#pragma unroll
    for (int j = 0; j < 8; j++) {
        int u = j * 256 + t;
        int row = u >> 3, c4 = u & 7;
        cp16(sb + (16640 + row * 36 + c4 * 4) * 4, xw + row * 32 + c4 * 4);
    }
    CP_COMMIT();
    CP_WAIT(0);
    __syncthreads();

    int m_t = wid >> 1;
    int n_t = wid & 1;
    wmma::fragment<wmma::accumulator, 16, 16, 8, float> acc;
    wmma::fill_fragment(acc, 0.0f);
#pragma unroll
    for (int k0 = 0; k0 < 32; k0++) {
        wmma::fragment<wmma::matrix_a, 16, 16, 8, wmma::precision::tf32, wmma::row_major> af;
        wmma::fragment<wmma::matrix_b, 16, 16, 8, wmma::precision::tf32, wmma::row_major> bf;
        wmma::load_matrix_sync(af, sm + (m_t * 16) * 260 + k0 * 8, 260);
        wmma::load_matrix_sync(bf, sX + (k0 * 8) * 36 + n_t * 16, 36);
        wmma::mma_sync(acc, af, bf, acc);
    }
    __syncthreads();
    float* sC = sX;
    wmma::store_matrix_sync(sC + (m_t * 16) * 36 + n_t * 16, acc, 36,
                            wmma::mem_row_major);
    __syncthreads();

#pragma unroll
    for (int r = 0; r < 2; r++) {
        int idx = r * 256 + t;
        int kxi = idx >> 4, ky = idx & 15;
        float re = sC[(2 * kxi) * 36 + 2 * ky]     + sC[(2 * kxi + 1) * 36 + 2 * ky + 1];
        float im = sC[(2 * kxi) * 36 + 2 * ky + 1] - sC[(2 * kxi + 1) * 36 + 2 * ky];
        d_Xf[(bc * 32 + kxi) * 16 + ky] = make_float2(re, im);
    }
}

// ---------------- stage C: per-mode channel mix -----------------------------------
__global__ void k_specmul() {
    int m = blockIdx.x;
    int half = m >> 8, kx = (m >> 4) & 15, ky = m & 15;
    int kxi = half * 16 + kx;
    __shared__ float2 sX[1024];
    __shared__ float2 sW[4096];
    for (int idx = threadIdx.x; idx < 1024; idx += 256) {
        int bv = idx >> 6, i = idx & 63;
        sX[idx] = d_Xf[((bv * 64 + i) * 32 + kxi) * 16 + ky];
    }
    for (int idx = threadIdx.x; idx < 4096; idx += 256)
        sW[idx] = d_wt[(size_t)m * 4096 + idx];
    __syncthreads();
#pragma unroll
    for (int k = 0; k < 4; k++) {
        int p = threadIdx.x + k * 256;
        int bv = p >> 6, o = p & 63;
        float re = 0.f, im = 0.f;
#pragma unroll 16
        for (int i = 0; i < 64; i++) {
            float2 xv = sX[bv * 64 + i];
            float2 wv = sW[i * 64 + o];
            re = fmaf(xv.x, wv.x, re); re = fmaf(-xv.y, wv.y, re);
            im = fmaf(xv.x, wv.y, im); im = fmaf( xv.y, wv.x, im);
        }
        d_Y[((bv * 64 + o) * 32 + kxi) * 16 + ky] = make_float2(re, im);
    }
}

// ---------------- stage D v2: inverse DFT over H via tf32 wmma ----------------------
// Per (b,o): C[h=256][ky2=32] = TEH[h=256][kx2=64] * Yc[kx2=64][ky2=32]
//   Yc rows: 2k = (Yr, Yi) interleaved by ky pair; 2k+1 = (-Yi, Yr)
//   => C[h][2ky] = re, C[h][2ky+1] = im (exact complex arithmetic)
// smem floats: A = TEH @0 [256][68] (17408; C [256][36] overlays), B @17408 [64][36].
// total 19712 f = 78848 B -> 2 CTAs/SM.
#define IDH_SMEM (19712*4)
__global__ void __launch_bounds__(256, 2)
k_idftH2() {
    extern __shared__ float sm[];
    uint32_t sb = smem_u32(sm);
    int bc = blockIdx.x;                 // b*64 + o
    int b = bc >> 6, o = bc & 63;
    int t = threadIdx.x, wid = t >> 5;
    float* fB = sm + 17408;

    // A table: 17408 floats = 4352 cp16 (17/thread)
#pragma unroll
    for (int j = 0; j < 17; j++) {
        int u = j * 256 + t;
        cp16(sb + u * 16, d_TEH + u * 4);
    }
    CP_COMMIT();
    // B: build from Y (coalesced 4KB read, scatter with complex structure)
#pragma unroll
    for (int j = 0; j < 2; j++) {
        int idx = j * 256 + t;           // 0..511
        float2 y = d_Y[(size_t)bc * 512 + idx];
        int kxi = idx >> 4, ky = idx & 15;
        fB[(2 * kxi) * 36 + 2 * ky]         = __uint_as_float(f2tf32(y.x));
        fB[(2 * kxi) * 36 + 2 * ky + 1]     = __uint_as_float(f2tf32(y.y));
        fB[(2 * kxi + 1) * 36 + 2 * ky]     = __uint_as_float(f2tf32(-y.y));
        fB[(2 * kxi + 1) * 36 + 2 * ky + 1] = __uint_as_float(f2tf32(y.x));
    }
    CP_WAIT(0);
    __syncthreads();

    // 16 m-tiles x 2 n-tiles over 8 warps: warp owns m_t in {2*wid, 2*wid+1}, both n
    wmma::fragment<wmma::accumulator, 16, 16, 8, float> acc[4];
#pragma unroll
    for (int q = 0; q < 4; q++) wmma::fill_fragment(acc[q], 0.0f);
#pragma unroll
    for (int k0 = 0; k0 < 8; k0++) {
#pragma unroll
        for (int mi = 0; mi < 2; mi++) {
            wmma::fragment<wmma::matrix_a, 16, 16, 8, wmma::precision::tf32, wmma::row_major> af;
            wmma::load_matrix_sync(af, sm + ((wid * 2 + mi) * 16) * 68 + k0 * 8, 68);
#pragma unroll
            for (int ni = 0; ni < 2; ni++) {
                wmma::fragment<wmma::matrix_b, 16, 16, 8, wmma::precision::tf32, wmma::row_major> bf;
                wmma::load_matrix_sync(bf, fB + (k0 * 8) * 36 + ni * 16, 36);
                wmma::mma_sync(acc[mi * 2 + ni], af, bf, acc[mi * 2 + ni]);
            }
        }
    }
    __syncthreads();                     // A reads done; C overlays A
    float* sC = sm;                      // [256][36]
#pragma unroll
    for (int mi = 0; mi < 2; mi++)
#pragma unroll
        for (int ni = 0; ni < 2; ni++)
            wmma::store_matrix_sync(sC + ((wid * 2 + mi) * 16) * 36 + ni * 16,
                                    acc[mi * 2 + ni], 36, wmma::mem_row_major);
    __syncthreads();

    // epilogue: thread owns h = t; scale + pack + store 16 float2 (128B contiguous)
    float2* zrow = d_Z + ((size_t)(b * 256 + t) * 64 + o) * 16;
#pragma unroll
    for (int ky = 0; ky < 16; ky++) {
        float sc = (ky ? 2.0f : 1.0f) * (1.0f / 65536.0f);
        float re = sC[t * 36 + 2 * ky]     * sc;
        float im = sC[t * 36 + 2 * ky + 1] * sc;
        zrow[ky] = make_float2(re, im);
    }
}

// ---------------- stage E v8: champion (R14) ----------------------------------------
#define LDA4 132
#define LDB4 68
#define LDCT 132
#define E_SMEM 60160

__global__ void __launch_bounds__(256, 3)
k_fusedE8(const float* __restrict__ x, const float* __restrict__ cb,
          float* __restrict__ out) {
    extern __shared__ float sm[];
    uint32_t sb = smem_u32(sm);
    float* fB  = sm + 8448;
    float* sCB = sm + 14976;

    int gx = blockIdx.x;
    int h = gx >> 1, wh = gx & 1;
    int b = blockIdx.y, t = threadIdx.x;
    int wid = t >> 5;

    const float* xbase = x + (size_t)b * 4194304 + (size_t)h * 256 + wh * 128;

#pragma unroll
    for (int j = 0; j < 4; j++) {
        int u = j * 256 + t;
        int il = u >> 5, w4 = u & 31;
        cp16(sb + (il * LDA4 + w4 * 4) * 4, xbase + (size_t)il * 65536 + w4 * 4);
    }
    CP_COMMIT();
#pragma unroll
    for (int j = 0; j < 4; j++) {
        int u = j * 256 + t;
        int row = u >> 4, c4 = u & 15;
        cp16(sb + (8448 + row * LDB4 + c4 * 4) * 4, d_cwT + row * 64 + c4 * 4);
    }
    CP_COMMIT();
#pragma unroll
    for (int j = 0; j < 4; j++) {
        int u = j * 256 + t;
        int il = u >> 5, w4 = u & 31;
        cp16(sb + (4224 + il * LDA4 + w4 * 4) * 4,
             xbase + (size_t)(32 + il) * 65536 + w4 * 4);
    }
    CP_COMMIT();

#pragma unroll
    for (int j = 0; j < 4; j++) {
        int idx = j * 256 + t;
        float2 z = d_Z[(size_t)(b * 256 + h) * 1024 + idx];
        int o = idx >> 4, ky = idx & 15;
        fB[(64 + 2 * ky) * LDB4 + o] = __uint_as_float(f2tf32(z.x));
        fB[(65 + 2 * ky) * LDB4 + o] = __uint_as_float(f2tf32(-z.y));
    }
    if (t < 64) sCB[t] = cb[t];

    wmma::fragment<wmma::accumulator, 16, 16, 8, float> acc[4];
#pragma unroll
    for (int n0 = 0; n0 < 4; n0++) wmma::fill_fragment(acc[n0], 0.0f);
    int m0 = wid * 16;

    CP_WAIT(1);
    __syncthreads();
#pragma unroll
    for (int j = 0; j < 4; j++) {
        wmma::fragment<wmma::matrix_a, 16, 16, 8, wmma::precision::tf32, wmma::col_major> af;
        wmma::load_matrix_sync(af, sm + j * 8 * LDA4 + m0, LDA4);
#pragma unroll
        for (int n0 = 0; n0 < 4; n0++) {
            wmma::fragment<wmma::matrix_b, 16, 16, 8, wmma::precision::tf32, wmma::row_major> bf;
            wmma::load_matrix_sync(bf, fB + j * 8 * LDB4 + n0 * 16, LDB4);
            wmma::mma_sync(acc[n0], af, bf, acc[n0]);
        }
    }
    __syncthreads();
#pragma unroll
    for (int j = 0; j < 4; j++) {
        int u = j * 256 + t;
        int kk = u >> 5, w4 = u & 31;
        cp16(sb + (kk * LDA4 + w4 * 4) * 4, d_TE + kk * 256 + wh * 128 + w4 * 4);
    }
    CP_COMMIT();

    CP_WAIT(1);
    __syncthreads();
#pragma unroll
    for (int j = 0; j < 4; j++) {
        wmma::fragment<wmma::matrix_a, 16, 16, 8, wmma::precision::tf32, wmma::col_major> af;
        wmma::load_matrix_sync(af, sm + 4224 + j * 8 * LDA4 + m0, LDA4);
#pragma unroll
        for (int n0 = 0; n0 < 4; n0++) {
            wmma::fragment<wmma::matrix_b, 16, 16, 8, wmma::precision::tf32, wmma::row_major> bf;
            wmma::load_matrix_sync(bf, fB + (32 + j * 8) * LDB4 + n0 * 16, LDB4);
            wmma::mma_sync(acc[n0], af, bf, acc[n0]);
        }
    }

    CP_WAIT(0);
    __syncthreads();
#pragma unroll
    for (int j = 0; j < 4; j++) {
        wmma::fragment<wmma::matrix_a, 16, 16, 8, wmma::precision::tf32, wmma::col_major> af;
        wmma::load_matrix_sync(af, sm + j * 8 * LDA4 + m0, LDA4);
#pragma unroll
        for (int n0 = 0; n0 < 4; n0++) {
            wmma::fragment<wmma::matrix_b, 16, 16, 8, wmma::precision::tf32, wmma::row_major> bf;
            wmma::load_matrix_sync(bf, fB + (64 + j * 8) * LDB4 + n0 * 16, LDB4);
            wmma::mma_sync(acc[n0], af, bf, acc[n0]);
        }
    }
    __syncthreads();
    float* sCT = sm;
#pragma unroll
    for (int n0 = 0; n0 < 4; n0++)
        wmma::store_matrix_sync(sCT + (n0 * 16) * LDCT + m0, acc[n0], LDCT,
                                wmma::mem_col_major);
    __syncthreads();

    int o = t >> 2, q = t & 3;
    float bias = sCB[o];
    float S = 0.f, Q = 0.f;
#pragma unroll
    for (int j = 0; j < 8; j++) {
        int wl = q * 32 + j * 4;
        float4 c4 = *(float4*)&sCT[o * LDCT + wl];
        float g0 = c4.x + bias, g1 = c4.y + bias, g2 = c4.z + bias, g3 = c4.w + bias;
        g0 = 0.5f * g0 * (1.0f + erff(g0 * 0.70710678118654752f));
        g1 = 0.5f * g1 * (1.0f + erff(g1 * 0.70710678118654752f));
        g2 = 0.5f * g2 * (1.0f + erff(g2 * 0.70710678118654752f));
        g3 = 0.5f * g3 * (1.0f + erff(g3 * 0.70710678118654752f));
        *(float4*)&sCT[o * LDCT + wl] = make_float4(g0, g1, g2, g3);
        S += g0 + g1 + g2 + g3;
        Q += g0 * g0 + g1 * g1 + g2 * g2 + g3 * g3;
    }
#pragma unroll
    for (int off = 1; off < 8; off <<= 1) {
        S += __shfl_xor_sync(0xffffffffu, S, off);
        Q += __shfl_xor_sync(0xffffffffu, Q, off);
    }
    if ((t & 7) == 0) {
        int g = t >> 3;
        int slot = h * 2 + wh;
        d_partS[(b * 32 + g) * 512 + slot] = S;
        d_partQ[(b * 32 + g) * 512 + slot] = Q;
    }
    __syncthreads();

    int lane = t & 31, row8 = t >> 5;
    float* obase = out + (size_t)b * 4194304 + (size_t)h * 256 + wh * 128 + lane * 4;
#pragma unroll
    for (int it = 0; it < 8; it++) {
        int och = it * 8 + row8;
        float4 v = *(float4*)&sCT[och * LDCT + lane * 4];
        *(float4*)(obase + (size_t)och * 65536) = v;
    }
}

// ---------------- stage R: group statistics ------------------------------------------
__global__ void k_stats2() {
    int bg = blockIdx.x;
    int t = threadIdx.x;
    __shared__ float rs[16], rq[16];
    float S = d_partS[bg * 512 + t];
    float Q = d_partQ[bg * 512 + t];
#pragma unroll
    for (int off = 16; off > 0; off >>= 1) {
        S += __shfl_xor_sync(0xffffffffu, S, off);
        Q += __shfl_xor_sync(0xffffffffu, Q, off);
    }
    if ((t & 31) == 0) { rs[t >> 5] = S; rq[t >> 5] = Q; }
    __syncthreads();
    if (t == 0) {
        float s = 0.f, q = 0.f;
#pragma unroll
        for (int k = 0; k < 16; k++) { s += rs[k]; q += rq[k]; }
        const float invN = 1.0f / 131072.0f;
        float mean = s * invN;
        float var  = q * invN - mean * mean;
        d_stat[bg] = make_float2(mean, 1.0f / sqrtf(var + 1e-5f));
    }
}

// ---------------- stage N: normalize ---------------------------------------------------
__global__ void k_norm(const float* __restrict__ gnw, const float* __restrict__ gnb,
                       float* __restrict__ out) {
    int idx = blockIdx.x * 256 + threadIdx.x;
    int e = idx << 2;
    int b = e >> 22;
    int c = (e >> 16) & 63;
    float2 st = d_stat[b * 32 + (c >> 1)];
    float sc = st.y * gnw[c];
    float sh = gnb[c] - st.x * sc;
    float4* o4 = (float4*)out;
    float4 v = o4[idx];
    v.x = fmaf(v.x, sc, sh); v.y = fmaf(v.y, sc, sh);
    v.z = fmaf(v.z, sc, sh); v.w = fmaf(v.w, sc, sh);
    o4[idx] = v;
}

// ---------------- launch -----------------------------------------------------------------
extern "C" void kernel_launch(void* const* d_in, const int* in_sizes, int n_in,
                              void* d_out, int out_size) {
    const float* x    = (const float*)d_in[0];
    const float* w1r  = (const float*)d_in[1];
    const float* w1i  = (const float*)d_in[2];
    const float* w2r  = (const float*)d_in[3];
    const float* w2i  = (const float*)d_in[4];
    const float* cw   = (const float*)d_in[5];
    const float* cb   = (const float*)d_in[6];
    const float* gnw  = (const float*)d_in[7];
    const float* gnb  = (const float*)d_in[8];
    float* out = (float*)d_out;

    cudaFuncSetAttribute(k_dftW3,   cudaFuncAttributeMaxDynamicSharedMemorySize, DW3_SMEM);
    cudaFuncSetAttribute(k_dftH2,   cudaFuncAttributeMaxDynamicSharedMemorySize, DH_SMEM);
    cudaFuncSetAttribute(k_idftH2,  cudaFuncAttributeMaxDynamicSharedMemorySize, IDH_SMEM);
    cudaFuncSetAttribute(k_fusedE8, cudaFuncAttributeMaxDynamicSharedMemorySize, E_SMEM);

    k_init<<<1, 256>>>();                              // 1
    k_transpose_w<<<8192, 256>>>(w1r, w1i, w2r, w2i);  // 2
    k_prepB<<<16, 256>>>(cw);                          // 3 (spacer + conv-B prep)
    k_dftW3<<<4096, 256, DW3_SMEM>>>(x);               // 4: PROFILED (clock sentinel)
    k_dftH2<<<1024, 256, DH_SMEM>>>();
    k_specmul<<<512, 256>>>();
    k_idftH2<<<1024, 256, IDH_SMEM>>>();
    k_fusedE8<<<dim3(512, 16), 256, E_SMEM>>>(x, cb, out);
    k_stats2<<<512, 512>>>();
    k_norm<<<65536, 256>>>(gnw, gnb, out);
}

// round 17
// speedup vs baseline: 1.0523x; 1.0523x over previous
#include <cuda_runtime.h>
#include <mma.h>
#include <math.h>
#include <cstdint>

using namespace nvcuda;

#define Bb 16
#define Cc 64
#define Hh 256
#define Ww 256
#define MM 16
#define SS 32

// ---------------- scratch ----------------------------------------------------
__device__ float2 d_tw[256];
__device__ float  d_TB[256*36];          // fwd trig (W), [w][ky2] pad, tf32-RNA
__device__ float  d_TE[32*256];          // inv trig (W), [kk][w], tf32-RNA
__device__ float  d_T2[64*260];          // fwd trig (H), [kx2][h] pad, tf32-RNA
__device__ float  d_cwT[64*64];          // tf32(conv_w^T + I), [i][o]
__device__ float2 d_Xw[Bb*Cc*Hh*MM];
__device__ float2 d_Xf[Bb*Cc*SS*MM];
__device__ float2 d_Y [Bb*Cc*SS*MM];
__device__ float2 d_Z [Bb*Hh*Cc*MM];
__device__ float2 d_wt[2*256*4096];
__device__ float  d_partS[Bb*32*256];
__device__ float  d_partQ[Bb*32*256];
__device__ float2 d_stat[Bb*32];

__device__ __forceinline__ uint32_t f2tf32(float f) {
    uint32_t r; asm("cvt.rna.tf32.f32 %0, %1;" : "=r"(r) : "f"(f)); return r;
}
__device__ __forceinline__ uint32_t smem_u32(const void* p) {
    uint32_t a;
    asm("{ .reg .u64 t; cvta.to.shared.u64 t, %1; cvt.u32.u64 %0, t; }" : "=r"(a) : "l"(p));
    return a;
}
__device__ __forceinline__ void cp16(uint32_t dst, const void* src) {
    asm volatile("cp.async.ca.shared.global [%0], [%1], 16;" :: "r"(dst), "l"(src));
}
#define CP_COMMIT()  asm volatile("cp.async.commit_group;" ::: "memory")
#define CP_WAIT(n)   asm volatile("cp.async.wait_group %0;" :: "n"(n) : "memory")

// ---------------- init: twiddles + tf32 trig tables ----------------------------
__global__ void k_init() {
    int t = threadIdx.x;
    float s, c;
    sincospif((float)t * (1.0f / 128.0f), &s, &c);
    d_tw[t] = make_float2(c, s);
#pragma unroll
    for (int kk = 0; kk < 32; kk++) {
        int ky = kk >> 1;
        float s2, c2;
        sincospif((float)((ky * t) & 255) * (1.0f / 128.0f), &s2, &c2);
        d_TB[t * 36 + kk] = __uint_as_float(f2tf32((kk & 1) ? -s2 : c2));
        d_TE[kk * 256 + t] = __uint_as_float(f2tf32((kk & 1) ?  s2 : c2));
    }
    d_TB[t * 36 + 32] = 0.f; d_TB[t * 36 + 33] = 0.f;
    d_TB[t * 36 + 34] = 0.f; d_TB[t * 36 + 35] = 0.f;
    for (int idx = t; idx < 64 * 260; idx += 256) {
        int m = idx / 260, h = idx % 260;
        int kxi = m >> 1;
        int kx = (kxi < 16) ? kxi : (224 + kxi);
        float v = 0.f;
        if (h < 256) {
            float s3, c3;
            sincospif((float)((kx * h) & 255) * (1.0f / 128.0f), &s3, &c3);
            v = (m & 1) ? s3 : c3;
        }
        d_T2[idx] = __uint_as_float(f2tf32(v));
    }
}

// ---------------- weight transpose --------------------------------------------
__global__ void k_transpose_w(const float* __restrict__ w1r, const float* __restrict__ w1i,
                              const float* __restrict__ w2r, const float* __restrict__ w2i) {
    int n = blockIdx.x * 256 + threadIdx.x;
    int half = n >> 20;
    int rem  = n & ((1 << 20) - 1);
    int mode = rem >> 12;
    int io   = rem & 4095;
    int kx = mode >> 4, ky = mode & 15;
    int i = io >> 6, o = io & 63;
    int src = ((i * 64 + o) * 16 + kx) * 16 + ky;
    const float* wr = half ? w2r : w1r;
    const float* wi = half ? w2i : w1i;
    d_wt[n] = make_float2(wr[src], wi[src]);
}

// ---------------- prep conv B (also profiling spacer) ---------------------------
__global__ void k_prepB(const float* __restrict__ cw) {
    int idx = blockIdx.x * 256 + threadIdx.x;
    int i = idx >> 6, o = idx & 63;
    float wv = cw[o * 64 + i] + ((i == o) ? 1.0f : 0.0f);
    d_cwT[idx] = __uint_as_float(f2tf32(wv));
}

// ---------------- stage A v3: DFT over W (champion) -----------------------------
#define LDX 260
#define LDTB 36
#define DW3_SMEM (25856*4)
__global__ void __launch_bounds__(256, 2)
k_dftW3(const float* __restrict__ x) {
    extern __shared__ float sm[];
    uint32_t sb = smem_u32(sm);
    int bx = blockIdx.x;
    int bc = bx >> 2, slab = bx & 3;
    int t = threadIdx.x, wid = t >> 5;
    float* sB = sm + 16640;
    const float* xblk = x + (size_t)bc * 65536 + slab * 16384;

#pragma unroll
    for (int j = 0; j < 16; j++) {
        int u = j * 256 + t;
        int hl = u >> 6, wu = u & 63;
        cp16(sb + (hl * LDX + wu * 4) * 4, xblk + hl * 256 + wu * 4);
    }
#pragma unroll
    for (int j = 0; j < 9; j++) {
        int u = j * 256 + t;
        cp16(sb + (16640 + u * 4) * 4, d_TB + u * 4);
    }
    CP_COMMIT();
    CP_WAIT(0);
    __syncthreads();

    int m_t = wid >> 1;
    int n_t = wid & 1;
    wmma::fragment<wmma::accumulator, 16, 16, 8, float> acc;
    wmma::fill_fragment(acc, 0.0f);
#pragma unroll
    for (int k0 = 0; k0 < 32; k0++) {
        wmma::fragment<wmma::matrix_a, 16, 16, 8, wmma::precision::tf32, wmma::row_major> af;
        wmma::fragment<wmma::matrix_b, 16, 16, 8, wmma::precision::tf32, wmma::row_major> bf;
        wmma::load_matrix_sync(af, sm + (m_t * 16) * LDX + k0 * 8, LDX);
        wmma::load_matrix_sync(bf, sB + (k0 * 8) * LDTB + n_t * 16, LDTB);
        wmma::mma_sync(acc, af, bf, acc);
    }
    __syncthreads();
    float* sC = sm;
    wmma::store_matrix_sync(sC + (m_t * 16) * LDTB + n_t * 16, acc, LDTB,
                            wmma::mem_row_major);
    __syncthreads();

    float4* dst = (float4*)(d_Xw + ((size_t)(bc << 8) + slab * 64) * 16);
#pragma unroll
    for (int r = 0; r < 2; r++) {
        int u = r * 256 + t;
        int row = u >> 3, c4 = u & 7;
        dst[row * 8 + c4] = *(float4*)&sC[row * LDTB + c4 * 4];
    }
}

// ---------------- stage B v2: DFT over H (champion) ------------------------------
#define DH_SMEM (25856*4)
__global__ void __launch_bounds__(256, 2)
k_dftH2() {
    extern __shared__ float sm[];
    uint32_t sb = smem_u32(sm);
    int bc = blockIdx.x;
    int t = threadIdx.x, wid = t >> 5;
    float* sX = sm + 16640;

#pragma unroll
    for (int j = 0; j < 17; j++) {
        int u = j * 256 + t;
        if (u < 4160) cp16(sb + u * 16, d_T2 + u * 4);
    }
    const float* xw = (const float*)(d_Xw + (size_t)bc * 4096);
#pragma unroll
    for (int j = 0; j < 8; j++) {
        int u = j * 256 + t;
        int row = u >> 3, c4 = u & 7;
        cp16(sb + (16640 + row * 36 + c4 * 4) * 4, xw + row * 32 + c4 * 4);
    }
    CP_COMMIT();
    CP_WAIT(0);
    __syncthreads();

    int m_t = wid >> 1;
    int n_t = wid & 1;
    wmma::fragment<wmma::accumulator, 16, 16, 8, float> acc;
    wmma::fill_fragment(acc, 0.0f);
#pragma unroll
    for (int k0 = 0; k0 < 32; k0++) {
        wmma::fragment<wmma::matrix_a, 16, 16, 8, wmma::precision::tf32, wmma::row_major> af;
        wmma::fragment<wmma::matrix_b, 16, 16, 8, wmma::precision::tf32, wmma::row_major> bf;
        wmma::load_matrix_sync(af, sm + (m_t * 16) * 260 + k0 * 8, 260);
        wmma::load_matrix_sync(bf, sX + (k0 * 8) * 36 + n_t * 16, 36);
        wmma::mma_sync(acc, af, bf, acc);
    }
    __syncthreads();
    float* sC = sX;
    wmma::store_matrix_sync(sC + (m_t * 16) * 36 + n_t * 16, acc, 36,
                            wmma::mem_row_major);
    __syncthreads();

#pragma unroll
    for (int r = 0; r < 2; r++) {
        int idx = r * 256 + t;
        int kxi = idx >> 4, ky = idx & 15;
        float re = sC[(2 * kxi) * 36 + 2 * ky]     + sC[(2 * kxi + 1) * 36 + 2 * ky + 1];
        float im = sC[(2 * kxi) * 36 + 2 * ky + 1] - sC[(2 * kxi + 1) * 36 + 2 * ky];
        d_Xf[(bc * 32 + kxi) * 16 + ky] = make_float2(re, im);
    }
}

// ---------------- stage C: per-mode channel mix -----------------------------------
__global__ void k_specmul() {
    int m = blockIdx.x;
    int half = m >> 8, kx = (m >> 4) & 15, ky = m & 15;
    int kxi = half * 16 + kx;
    __shared__ float2 sX[1024];
    __shared__ float2 sW[4096];
    for (int idx = threadIdx.x; idx < 1024; idx += 256) {
        int bv = idx >> 6, i = idx & 63;
        sX[idx] = d_Xf[((bv * 64 + i) * 32 + kxi) * 16 + ky];
    }
    for (int idx = threadIdx.x; idx < 4096; idx += 256)
        sW[idx] = d_wt[(size_t)m * 4096 + idx];
    __syncthreads();
#pragma unroll
    for (int k = 0; k < 4; k++) {
        int p = threadIdx.x + k * 256;
        int bv = p >> 6, o = p & 63;
        float re = 0.f, im = 0.f;
#pragma unroll 16
        for (int i = 0; i < 64; i++) {
            float2 xv = sX[bv * 64 + i];
            float2 wv = sW[i * 64 + o];
            re = fmaf(xv.x, wv.x, re); re = fmaf(-xv.y, wv.y, re);
            im = fmaf(xv.x, wv.y, im); im = fmaf( xv.y, wv.x, im);
        }
        d_Y[((bv * 64 + o) * 32 + kxi) * 16 + ky] = make_float2(re, im);
    }
}

// ---------------- stage D: inverse DFT over H (scalar, champion) --------------------
__global__ void k_idftH() {
    int bc = blockIdx.x;
    int b = bc >> 6, o = bc & 63;
    __shared__ float2 sY[512];
    __shared__ float2 stw[256];
    if (threadIdx.x < 256) stw[threadIdx.x] = d_tw[threadIdx.x];
    for (int idx = threadIdx.x; idx < 512; idx += 256)
        sY[idx] = d_Y[bc * 512 + idx];
    __syncthreads();
    int h = threadIdx.x;
    float ar[16], ai[16];
#pragma unroll
    for (int ky = 0; ky < 16; ky++) { ar[ky] = 0.f; ai[ky] = 0.f; }
#pragma unroll
    for (int kxi = 0; kxi < 32; kxi++) {
        int kx = (kxi < 16) ? kxi : (224 + kxi);
        float2 tv = stw[(kx * h) & 255];
#pragma unroll
        for (int ky = 0; ky < 16; ky++) {
            float2 y = sY[kxi * 16 + ky];
            ar[ky] = fmaf(y.x, tv.x, ar[ky]); ar[ky] = fmaf(-y.y, tv.y, ar[ky]);
            ai[ky] = fmaf(y.x, tv.y, ai[ky]); ai[ky] = fmaf( y.y, tv.x, ai[ky]);
        }
    }
#pragma unroll
    for (int ky = 0; ky < 16; ky++) {
        float sc = (ky ? 2.0f : 1.0f) * (1.0f / 65536.0f);
        d_Z[((b * 256 + h) * 64 + o) * 16 + ky] = make_float2(ar[ky] * sc, ai[ky] * sc);
    }
}

// ---------------- stage E v9: wh-fused GEMM, one block per (b,h) --------------------
// C[w=256][o=64] = sum_k A[k][w]*B[k][o], K=96 (x0-31 | x32-63 | trig).
// smem floats: A0 @0 [32][260], A1 @8320 [32][260] (C^T [64][260] overlays),
//              B @16640 [96][68], bias @23168. total 23232 f = 92928 B. 2 CTAs/SM.
#define LDA9 260
#define LDB9 68
#define LDC9 260
#define E9_SMEM (23232*4)

__global__ void __launch_bounds__(256, 2)
k_fusedE9(const float* __restrict__ x, const float* __restrict__ cb,
          float* __restrict__ out) {
    extern __shared__ float sm[];
    uint32_t sb = smem_u32(sm);
    float* fB  = sm + 16640;
    float* sCB = sm + 23168;

    int h = blockIdx.x, b = blockIdx.y, t = threadIdx.x;
    int wid = t >> 5;

    const float* xbase = x + (size_t)b * 4194304 + (size_t)h * 256;

    // G1: A0 <- x channels 0..31 (full 256-w rows)
#pragma unroll
    for (int j = 0; j < 8; j++) {
        int u = j * 256 + t;
        int il = u >> 6, w4 = u & 63;
        cp16(sb + (il * LDA9 + w4 * 4) * 4, xbase + (size_t)il * 65536 + w4 * 4);
    }
    CP_COMMIT();
    // G2: B conv rows 0..63
#pragma unroll
    for (int j = 0; j < 4; j++) {
        int u = j * 256 + t;
        int row = u >> 4, c4 = u & 15;
        cp16(sb + (16640 + row * LDB9 + c4 * 4) * 4, d_cwT + row * 64 + c4 * 4);
    }
    CP_COMMIT();
    // G3: A1 <- x channels 32..63
#pragma unroll
    for (int j = 0; j < 8; j++) {
        int u = j * 256 + t;
        int il = u >> 6, w4 = u & 63;
        cp16(sb + (8320 + il * LDA9 + w4 * 4) * 4,
             xbase + (size_t)(32 + il) * 65536 + w4 * 4);
    }
    CP_COMMIT();

    // manual: B Z-rows + bias (Z read ONCE per (b,h))
#pragma unroll
    for (int j = 0; j < 4; j++) {
        int idx = j * 256 + t;
        float2 z = d_Z[(size_t)(b * 256 + h) * 1024 + idx];
        int o = idx >> 4, ky = idx & 15;
        fB[(64 + 2 * ky) * LDB9 + o] = __uint_as_float(f2tf32(z.x));
        fB[(65 + 2 * ky) * LDB9 + o] = __uint_as_float(f2tf32(-z.y));
    }
    if (t < 64) sCB[t] = cb[t];

    // warp owns m-tiles {2*wid, 2*wid+1} x 4 n-tiles
    wmma::fragment<wmma::accumulator, 16, 16, 8, float> acc[8];
#pragma unroll
    for (int q = 0; q < 8; q++) wmma::fill_fragment(acc[q], 0.0f);

    // ---- chunk 0: A0 x B rows 0..31 ----
    CP_WAIT(1);
    __syncthreads();
#pragma unroll
    for (int j = 0; j < 4; j++) {
#pragma unroll
        for (int mi = 0; mi < 2; mi++) {
            wmma::fragment<wmma::matrix_a, 16, 16, 8, wmma::precision::tf32, wmma::col_major> af;
            wmma::load_matrix_sync(af, sm + j * 8 * LDA9 + (wid * 2 + mi) * 16, LDA9);
#pragma unroll
            for (int n0 = 0; n0 < 4; n0++) {
                wmma::fragment<wmma::matrix_b, 16, 16, 8, wmma::precision::tf32, wmma::row_major> bf;
                wmma::load_matrix_sync(bf, fB + j * 8 * LDB9 + n0 * 16, LDB9);
                wmma::mma_sync(acc[mi * 4 + n0], af, bf, acc[mi * 4 + n0]);
            }
        }
    }
    __syncthreads();                     // A0 free -> refill with trig (full 256 w)
#pragma unroll
    for (int j = 0; j < 8; j++) {
        int u = j * 256 + t;
        int kk = u >> 6, w4 = u & 63;
        cp16(sb + (kk * LDA9 + w4 * 4) * 4, d_TE + kk * 256 + w4 * 4);
    }
    CP_COMMIT();

    // ---- chunk 1: A1 x B rows 32..63 ----
    CP_WAIT(1);
    __syncthreads();
#pragma unroll
    for (int j = 0; j < 4; j++) {
#pragma unroll
        for (int mi = 0; mi < 2; mi++) {
            wmma::fragment<wmma::matrix_a, 16, 16, 8, wmma::precision::tf32, wmma::col_major> af;
            wmma::load_matrix_sync(af, sm + 8320 + j * 8 * LDA9 + (wid * 2 + mi) * 16, LDA9);
#pragma unroll
            for (int n0 = 0; n0 < 4; n0++) {
                wmma::fragment<wmma::matrix_b, 16, 16, 8, wmma::precision::tf32, wmma::row_major> bf;
                wmma::load_matrix_sync(bf, fB + (32 + j * 8) * LDB9 + n0 * 16, LDB9);
                wmma::mma_sync(acc[mi * 4 + n0], af, bf, acc[mi * 4 + n0]);
            }
        }
    }

    // ---- chunk 2: A0(trig) x B rows 64..95 ----
    CP_WAIT(0);
    __syncthreads();
#pragma unroll
    for (int j = 0; j < 4; j++) {
#pragma unroll
        for (int mi = 0; mi < 2; mi++) {
            wmma::fragment<wmma::matrix_a, 16, 16, 8, wmma::precision::tf32, wmma::col_major> af;
            wmma::load_matrix_sync(af, sm + j * 8 * LDA9 + (wid * 2 + mi) * 16, LDA9);
#pragma unroll
            for (int n0 = 0; n0 < 4; n0++) {
                wmma::fragment<wmma::matrix_b, 16, 16, 8, wmma::precision::tf32, wmma::row_major> bf;
                wmma::load_matrix_sync(bf, fB + (64 + j * 8) * LDB9 + n0 * 16, LDB9);
                wmma::mma_sync(acc[mi * 4 + n0], af, bf, acc[mi * 4 + n0]);
            }
        }
    }
    __syncthreads();                     // A reads done; C^T overlays A0+A1
    float* sCT = sm;                     // [o=64][w=256], ld=LDC9
#pragma unroll
    for (int mi = 0; mi < 2; mi++)
#pragma unroll
        for (int n0 = 0; n0 < 4; n0++)
            wmma::store_matrix_sync(sCT + (n0 * 16) * LDC9 + (wid * 2 + mi) * 16,
                                    acc[mi * 4 + n0], LDC9, wmma::mem_col_major);
    __syncthreads();

    // ---- phase 1: channel-major GELU in smem + partials ----
    int o = t >> 2, q = t & 3;
    float bias = sCB[o];
    float S = 0.f, Q = 0.f;
#pragma unroll
    for (int j = 0; j < 16; j++) {
        int wl = q * 64 + j * 4;
        float4 c4 = *(float4*)&sCT[o * LDC9 + wl];
        float g0 = c4.x + bias, g1 = c4.y + bias, g2 = c4.z + bias, g3 = c4.w + bias;
        g0 = 0.5f * g0 * (1.0f + erff(g0 * 0.70710678118654752f));
        g1 = 0.5f * g1 * (1.0f + erff(g1 * 0.70710678118654752f));
        g2 = 0.5f * g2 * (1.0f + erff(g2 * 0.70710678118654752f));
        g3 = 0.5f * g3 * (1.0f + erff(g3 * 0.70710678118654752f));
        *(float4*)&sCT[o * LDC9 + wl] = make_float4(g0, g1, g2, g3);
        S += g0 + g1 + g2 + g3;
        Q += g0 * g0 + g1 * g1 + g2 * g2 + g3 * g3;
    }
#pragma unroll
    for (int off = 1; off < 8; off <<= 1) {
        S += __shfl_xor_sync(0xffffffffu, S, off);
        Q += __shfl_xor_sync(0xffffffffu, Q, off);
    }
    if ((t & 7) == 0) {
        int g = t >> 3;
        d_partS[(b * 32 + g) * 256 + h] = S;
        d_partQ[(b * 32 + g) * 256 + h] = Q;
    }
    __syncthreads();

    // ---- phase 2: w-major vectorized coalesced stores ----
    int lane = t & 31, row8 = t >> 5;
    float* obase = out + (size_t)b * 4194304 + (size_t)h * 256;
#pragma unroll
    for (int it = 0; it < 8; it++) {
        int och = it * 8 + row8;
#pragma unroll
        for (int p = 0; p < 2; p++) {
            int w4 = lane + p * 32;
            float4 v = *(float4*)&sCT[och * LDC9 + w4 * 4];
            *(float4*)(obase + (size_t)och * 65536 + w4 * 4) = v;
        }
    }
}

// ---------------- stage R: group statistics (256 partials) ---------------------------
__global__ void k_stats3() {
    int bg = blockIdx.x;
    int t = threadIdx.x;                 // 256
    __shared__ float rs[8], rq[8];
    float S = d_partS[bg * 256 + t];
    float Q = d_partQ[bg * 256 + t];
#pragma unroll
    for (int off = 16; off > 0; off >>= 1) {
        S += __shfl_xor_sync(0xffffffffu, S, off);
        Q += __shfl_xor_sync(0xffffffffu, Q, off);
    }
    if ((t & 31) == 0) { rs[t >> 5] = S; rq[t >> 5] = Q; }
    __syncthreads();
    if (t == 0) {
        float s = 0.f, q = 0.f;
#pragma unroll
        for (int k = 0; k < 8; k++) { s += rs[k]; q += rq[k]; }
        const float invN = 1.0f / 131072.0f;
        float mean = s * invN;
        float var  = q * invN - mean * mean;
        d_stat[bg] = make_float2(mean, 1.0f / sqrtf(var + 1e-5f));
    }
}

// ---------------- stage N: normalize ---------------------------------------------------
__global__ void k_norm(const float* __restrict__ gnw, const float* __restrict__ gnb,
                       float* __restrict__ out) {
    int idx = blockIdx.x * 256 + threadIdx.x;
    int e = idx << 2;
    int b = e >> 22;
    int c = (e >> 16) & 63;
    float2 st = d_stat[b * 32 + (c >> 1)];
    float sc = st.y * gnw[c];
    float sh = gnb[c] - st.x * sc;
    float4* o4 = (float4*)out;
    float4 v = o4[idx];
    v.x = fmaf(v.x, sc, sh); v.y = fmaf(v.y, sc, sh);
    v.z = fmaf(v.z, sc, sh); v.w = fmaf(v.w, sc, sh);
    o4[idx] = v;
}

// ---------------- launch -----------------------------------------------------------------
extern "C" void kernel_launch(void* const* d_in, const int* in_sizes, int n_in,
                              void* d_out, int out_size) {
    const float* x    = (const float*)d_in[0];
    const float* w1r  = (const float*)d_in[1];
    const float* w1i  = (const float*)d_in[2];
    const float* w2r  = (const float*)d_in[3];
    const float* w2i  = (const float*)d_in[4];
    const float* cw   = (const float*)d_in[5];
    const float* cb   = (const float*)d_in[6];
    const float* gnw  = (const float*)d_in[7];
    const float* gnb  = (const float*)d_in[8];
    float* out = (float*)d_out;

    cudaFuncSetAttribute(k_dftW3,   cudaFuncAttributeMaxDynamicSharedMemorySize, DW3_SMEM);
    cudaFuncSetAttribute(k_dftH2,   cudaFuncAttributeMaxDynamicSharedMemorySize, DH_SMEM);
    cudaFuncSetAttribute(k_fusedE9, cudaFuncAttributeMaxDynamicSharedMemorySize, E9_SMEM);

    k_init<<<1, 256>>>();                              // 1
    k_transpose_w<<<8192, 256>>>(w1r, w1i, w2r, w2i);  // 2
    k_prepB<<<16, 256>>>(cw);                          // 3 (spacer + conv-B prep)
    k_dftW3<<<4096, 256, DW3_SMEM>>>(x);               // 4: PROFILED (clock sentinel)
    k_dftH2<<<1024, 256, DH_SMEM>>>();
    k_specmul<<<512, 256>>>();
    k_idftH<<<1024, 256>>>();
    k_fusedE9<<<dim3(256, 16), 256, E9_SMEM>>>(x, cb, out);
    k_stats3<<<512, 256>>>();
    k_norm<<<65536, 256>>>(gnw, gnb, out);
}